// round 15
// baseline (speedup 1.0000x reference)
#include <cuda_runtime.h>
#include <cuda_fp16.h>

#define BSZ    2048
#define TT     128
#define NN     256
#define MM     256
#define GG4    1024
#define B_TILE 16
#define GB     8               /* batches per group */
#define GST    8               /* state j-stride (aligned, broadcast reads) */
#define NBLK   (BSZ / B_TILE)  /* 128 */
#define NTHR   1024
#define GRP    512

// ---------------- device scratch ----------------
__device__ __half g_Ux[(size_t)BSZ * TT * NN];   // [b][s][n] fp16, 134 MB
__device__ uint4  g_Wth [64 * 1024];             // [k8][r] : 8 consecutive fp16 k of row r (r = g*256+m)
__device__ uint4  g_WtEh[16 * 128];              // [k8][s] : 8 consecutive fp16 k of W_e row s

// ---------------- fast math ----------------
__device__ __forceinline__ float ex2f(float x) {
    float r; asm("ex2.approx.f32 %0, %1;" : "=f"(r) : "f"(x)); return r;
}
__device__ __forceinline__ float rcpf(float x) {
    float r; asm("rcp.approx.f32 %0, %1;" : "=f"(r) : "f"(x)); return r;
}
#define L2E 1.4426950408889634f
__device__ __forceinline__ float tanh_fast(float x) {      // precise path (cell update)
    float t = ex2f(2.0f * L2E * x);
    return 1.0f - 2.0f * rcpf(t + 1.0f);
}
__device__ __forceinline__ float sigmoid_fast(float x) {
    return rcpf(1.0f + ex2f(-L2E * x));
}
__device__ __forceinline__ unsigned tanh2_h(unsigned x) {  // f16x2 hw tanh (attention only)
    unsigned r; asm("tanh.approx.f16x2 %0, %1;" : "=r"(r) : "r"(x)); return r;
}

// ---------------- packed f32x2 ----------------
typedef unsigned long long u64;
__device__ __forceinline__ u64 pack2(float a, float b) {
    u64 r; asm("mov.b64 %0, {%1, %2};" : "=l"(r) : "f"(a), "f"(b)); return r;
}
__device__ __forceinline__ void unpack2(u64 v, float& a, float& b) {
    asm("mov.b64 {%0, %1}, %2;" : "=f"(a), "=f"(b) : "l"(v));
}
__device__ __forceinline__ u64 ffma2(u64 a, u64 b, u64 c) {
    u64 d; asm("fma.rn.f32x2 %0, %1, %2, %3;" : "=l"(d) : "l"(a), "l"(b), "l"(c)); return d;
}
__device__ __forceinline__ u64 add2(u64 a, u64 b) {
    u64 d; asm("add.rn.f32x2 %0, %1, %2;" : "=l"(d) : "l"(a), "l"(b)); return d;
}
__device__ __forceinline__ void stcs(float* p, float v) {
    asm volatile("st.global.cs.f32 [%0], %1;" :: "l"(p), "f"(v) : "memory");
}
__device__ __forceinline__ unsigned pack_h2(float lo, float hi) {
    __half2 h = __floats2half2_rn(lo, hi);
    return *(unsigned*)&h;
}
__device__ __forceinline__ void wdup2_h(unsigned w32, u64& wpE, u64& wpO) {
    __half2 hw = *(__half2*)&w32;
    float2 fw = __half22float2(hw);
    wpE = pack2(fw.x, fw.x);
    wpO = pack2(fw.y, fw.y);
}
// group-scoped named barrier (ids 1 and 2), 512 threads each
#define GBAR(gid) asm volatile("bar.sync %0, %1;" :: "r"((gid) + 1), "r"(GRP) : "memory")

// =====================================================================
// Kernel 1: Ux precompute (+ fp16 weight transpose in trailing blocks).
// =====================================================================
__global__ void __launch_bounds__(256, 1) ux_kernel(
    const float* __restrict__ x,    const float* __restrict__ U_e,
    const float* __restrict__ W_ih, const float* __restrict__ W_hh,
    const float* __restrict__ W_e)
{
    if (blockIdx.x >= BSZ) {   // ---- transpose + fp16 convert ----
        int idx = (blockIdx.x - BSZ) * 256 + threadIdx.x;
        if (idx < 64 * 1024) {
            int k8 = idx >> 10, r = idx & 1023;
            const float* src = (k8 < 32) ? (W_ih + r * 256 + k8 * 8)
                                         : (W_hh + r * 256 + (k8 - 32) * 8);
            float4 a = *(const float4*)(src);
            float4 b = *(const float4*)(src + 4);
            uint4 o;
            o.x = pack_h2(a.x, a.y); o.y = pack_h2(a.z, a.w);
            o.z = pack_h2(b.x, b.y); o.w = pack_h2(b.z, b.w);
            g_Wth[idx] = o;
        } else if (idx < 64 * 1024 + 16 * 128) {
            int j = idx - 64 * 1024;       // j = k8*128 + s
            int k8 = j >> 7, s = j & 127;
            const float* src = W_e + s * 512 + k8 * 8;
            float4 a = *(const float4*)(src);
            float4 b = *(const float4*)(src + 4);
            uint4 o;
            o.x = pack_h2(a.x, a.y); o.y = pack_h2(a.z, a.w);
            o.z = pack_h2(b.x, b.y); o.w = pack_h2(b.z, b.w);
            g_WtEh[j] = o;
        }
        return;
    }

    extern __shared__ float sm[];
    float* x_s  = sm;                    // [TT][NN]
    u64*   U2_s = (u64*)(sm + TT * NN);  // [64 s-pairs][128 t]
    float* U2f  = (float*)U2_s;

    const int b   = blockIdx.x;
    const int tid = threadIdx.x;

    const float4* xg = (const float4*)(x + (size_t)b * TT * NN);
    float4* xs4 = (float4*)x_s;
    for (int i = tid; i < TT * NN / 4; i += 256) xs4[i] = xg[i];

    for (int i = tid; i < TT * TT / 4; i += 256) {
        float4 v = ((const float4*)U_e)[i];
        int s  = i >> 5;
        int t0 = (i & 31) * 4;
        #pragma unroll
        for (int q = 0; q < 4; q++)
            U2f[(((s >> 1) * 128) + (t0 + q)) * 2 + (s & 1)] = (&v.x)[q];
    }
    __syncthreads();

    const int n = tid;
    for (int chunk = 0; chunk < 8; chunk++) {
        u64 acc[8];
        #pragma unroll
        for (int i = 0; i < 8; i++) acc[i] = 0ull;
        #pragma unroll 2
        for (int t = 0; t < TT; t++) {
            float xv = x_s[t * NN + n];
            u64 xp = pack2(xv, xv);
            #pragma unroll
            for (int i = 0; i < 8; i++)
                acc[i] = ffma2(U2_s[(chunk * 8 + i) * 128 + t], xp, acc[i]);
        }
        #pragma unroll
        for (int i = 0; i < 8; i++) {
            float a, bb; unpack2(acc[i], a, bb);
            #pragma unroll
            for (int h = 0; h < 2; h++) {
                float v = h ? bb : a;
                int s = chunk * 16 + 2 * i + h;
                float vn = __shfl_down_sync(0xffffffffu, v, 1);
                if ((n & 1) == 0) {
                    __half2 hv = __floats2half2_rn(v, vn);
                    *((__half2*)(g_Ux + ((size_t)b * TT + s) * NN + n)) = hv;
                }
            }
        }
    }
}

// =====================================================================
// Kernel 2: persistent recurrence. 128 CTAs x 1024 threads = TWO fully
// independent 8-batch groups per CTA (named barriers, private smem).
// Groups drift out of phase -> D-FMA of one overlaps B-DRAM of the other.
// =====================================================================
__global__ void __launch_bounds__(NTHR, 1) rec_kernel(
    const float* __restrict__ V_e,
    const float* __restrict__ b_ih, const float* __restrict__ b_hh,
    float* __restrict__ out)
{
    extern __shared__ float sm[];
    // per-group slices sized [2][...]; group g offset = g * (sub-size)
    float*    h_all  = sm;                         // [2][MM][GST]    8192 f
    float*    c_all  = h_all + 2 * MM * GST;       // [2][MM][GST]    8192 f
    float*    xt_all = c_all + 2 * MM * GST;       // [2][NN][GST]    8192 f
    float*    e_all  = xt_all + 2 * NN * GST;      // [2][GB][NN]     4096 f
    float*    bs_s   = e_all + 2 * GB * NN;        // [GG4]           1024 f
    float*    V_s    = bs_s + GG4;                 // [TT]            128 f
    unsigned* whs_all = (unsigned*)(V_s + TT);     // [2][TT][GB]     2048 w
    u64*      un_all  = (u64*)(whs_all + 2 * TT * GB); // [2][4096] u64 : A-red [4][4][128] / D-gates [4][4][256]

    const int tid = threadIdx.x;
    const int gid = tid >> 9;                      // group 0/1
    const int ltid = tid & (GRP - 1);              // 0..511
    const int b0g  = blockIdx.x * B_TILE + gid * GB;

    // group-local pointers
    float*    h_s  = h_all  + gid * MM * GST;
    float*    c_s  = c_all  + gid * MM * GST;
    float*    xt_s = xt_all + gid * NN * GST;
    float*    e_s  = e_all  + gid * GB * NN;
    unsigned* whs2 = whs_all + gid * TT * GB;
    u64*      un_s = un_all  + gid * 4096;

    // full-CTA init (single __syncthreads, before groups diverge)
    for (int i = tid; i < 4 * MM * GST; i += NTHR) h_all[i] = 0.0f;  // h + c both groups
    for (int i = tid; i < TT;  i += NTHR) V_s[i]  = V_e[i];
    for (int i = tid; i < GG4; i += NTHR) bs_s[i] = b_ih[i] + b_hh[i];
    __syncthreads();

    // ---- per-phase thread mappings (within a 512-thread group) ----
    // A1: (sA 128, kg 4) ; kg 0-1 -> h halves, 2-3 -> c halves
    const int sA  = ltid & 127;
    const int kg  = ltid >> 7;                  // 0..3
    const float* aState = (kg < 2) ? h_s : c_s;
    const int    aKBase = (kg & 1) * 128;       // local k base
    // A2: (rs 128, rp 4)
    const int rs  = ltid & 127;
    const int rp  = ltid >> 7;
    // B: (np 128, jgB 4) -> 2 batches each
    const int np  = ltid & 127;
    const int n0  = np * 2;
    const int jgB = ltid >> 7;                  // 0..3 (warp-uniform)
    // C: group warps 0..7 = batch
    const int warpL = ltid >> 5, lane = ltid & 31;
    // D accum: (mD 256, gpD 2)
    const int mD  = ltid & 255;
    const int gpD = ltid >> 8;                  // 0/1 -> gates {i,f} / {g,o}
    // D epilogue: (mD, jq 2) -> 4 j each
    const int jq  = ltid >> 8;
    const int j0  = jq * 4;

    const __half2* ux2[2];
    #pragma unroll
    for (int jj = 0; jj < 2; jj++)
        ux2[jj] = (const __half2*)(g_Ux + ((size_t)(b0g + jgB * 2 + jj) * TT) * NN + n0);

    const int r0 = gpD * 512 + mD;              // weight row of gate gpD*2
    const u64 bpA = pack2(bs_s[r0],        bs_s[r0]);
    const u64 bpB = pack2(bs_s[r0 + 256],  bs_s[r0 + 256]);
    const uint4* wE = g_WtEh + sA;

    for (int t = 0; t < TT; t++) {
        // ---------- Phase A1: partial whs, k-split over 4 groups ----------
        {
            u64 acc[4] = {0ull, 0ull, 0ull, 0ull};
            #pragma unroll 2
            for (int i = 0; i < 16; i++) {                   // 16 k8-groups of 8 k
                uint4 wv = wE[(kg * 16 + i) * 128];
                #pragma unroll
                for (int q = 0; q < 4; q++) {
                    unsigned w32 = ((const unsigned*)&wv)[q];
                    u64 wpE, wpO; wdup2_h(w32, wpE, wpO);
                    #pragma unroll
                    for (int sub = 0; sub < 2; sub++) {
                        u64 wp = sub ? wpO : wpE;
                        const int k = aKBase + i * 8 + q * 2 + sub;
                        const float* st = &aState[k * GST];
                        ulonglong2 s0 = *(const ulonglong2*)&st[0];
                        ulonglong2 s1 = *(const ulonglong2*)&st[4];
                        acc[0] = ffma2(wp, s0.x, acc[0]);
                        acc[1] = ffma2(wp, s0.y, acc[1]);
                        acc[2] = ffma2(wp, s1.x, acc[2]);
                        acc[3] = ffma2(wp, s1.y, acc[3]);
                    }
                }
            }
            // layout [kg][p][sA] so A2 reads are lane-coalesced
            #pragma unroll
            for (int p = 0; p < 4; p++) un_s[(kg * 4 + p) * 128 + sA] = acc[p];
        }
        GBAR(gid);

        // ---------- Phase A2: reduce 4 partials -> whs2 ----------
        {
            u64 sum = un_s[(0 * 4 + rp) * 128 + rs];
            #pragma unroll
            for (int g2 = 1; g2 < 4; g2++)
                sum = add2(sum, un_s[(g2 * 4 + rp) * 128 + rs]);
            float f0, f1; unpack2(sum, f0, f1);
            __half2 p0 = __half2half2(__float2half_rn(f0));
            __half2 p1 = __half2half2(__float2half_rn(f1));
            whs2[rs * GB + rp * 2 + 0] = *(unsigned*)&p0;
            whs2[rs * GB + rp * 2 + 1] = *(unsigned*)&p1;
        }
        GBAR(gid);

        // ---------- Phase B: e[j][n] = sum_s V[s] * tanh(Ux + whs) ----------
        {
            float ex0[2] = {0, 0}, ex1[2] = {0, 0};
            #pragma unroll 4
            for (int s = 0; s < TT; s++) {
                uint2 wpk = *(const uint2*)&whs2[s * GB + jgB * 2];  // broadcast
                float vs = V_s[s];
                #pragma unroll
                for (int jj = 0; jj < 2; jj++) {
                    __half2 u   = ux2[jj][s * (NN / 2)];
                    __half2 wv  = *(__half2*)(((unsigned*)&wpk) + jj);
                    __half2 arg = __hadd2(u, wv);
                    unsigned th = tanh2_h(*(unsigned*)&arg);
                    float2 f = __half22float2(*(__half2*)&th);
                    ex0[jj] = fmaf(vs, f.x, ex0[jj]);
                    ex1[jj] = fmaf(vs, f.y, ex1[jj]);
                }
            }
            #pragma unroll
            for (int jj = 0; jj < 2; jj++) {
                float2 v = make_float2(ex0[jj], ex1[jj]);
                *(float2*)&e_s[(jgB * 2 + jj) * NN + n0] = v;
            }
        }
        GBAR(gid);

        // ---------- Phase C: softmax over n, xt = alpha * e (group warps 0..7) ----------
        if (warpL < GB) {
            const int j = warpL;
            float ev[8];
            float mx = -3.4e38f;
            #pragma unroll
            for (int i = 0; i < 8; i++) {
                ev[i] = e_s[j * NN + lane + 32 * i];
                mx = fmaxf(mx, ev[i]);
            }
            #pragma unroll
            for (int o = 16; o > 0; o >>= 1) mx = fmaxf(mx, __shfl_xor_sync(0xffffffffu, mx, o));
            float ax[8], sum = 0.0f;
            #pragma unroll
            for (int i = 0; i < 8; i++) { ax[i] = ex2f((ev[i] - mx) * L2E); sum += ax[i]; }
            #pragma unroll
            for (int o = 16; o > 0; o >>= 1) sum += __shfl_xor_sync(0xffffffffu, sum, o);
            float inv = rcpf(sum);
            #pragma unroll
            for (int i = 0; i < 8; i++)
                xt_s[(lane + 32 * i) * GST + j] = (ax[i] * inv) * ev[i];
        }
        GBAR(gid);

        // ---------- Phase D accum: (mD, gate-pair) x all 8 batches ----------
        {
            u64 a0[4], a1[4];
            #pragma unroll
            for (int p = 0; p < 4; p++) { a0[p] = bpA; a1[p] = bpB; }

            #pragma unroll 2
            for (int k8 = 0; k8 < 64; k8++) {
                uint4 wv0 = g_Wth[k8 * 1024 + r0];
                uint4 wv1 = g_Wth[k8 * 1024 + r0 + 256];
                const float* stb = (k8 < 32) ? xt_s : h_s;
                const int kb = (k8 & 31) * 8;
                #pragma unroll
                for (int q = 0; q < 4; q++) {
                    unsigned u0 = ((const unsigned*)&wv0)[q];
                    unsigned u1 = ((const unsigned*)&wv1)[q];
                    u64 wp0E, wp0O; wdup2_h(u0, wp0E, wp0O);
                    u64 wp1E, wp1O; wdup2_h(u1, wp1E, wp1O);
                    #pragma unroll
                    for (int sub = 0; sub < 2; sub++) {
                        u64 wp0 = sub ? wp0O : wp0E;
                        u64 wp1 = sub ? wp1O : wp1E;
                        const int k = kb + q * 2 + sub;
                        ulonglong2 sa = *(const ulonglong2*)&stb[k * GST];
                        ulonglong2 sb = *(const ulonglong2*)&stb[k * GST + 4];
                        a0[0] = ffma2(wp0, sa.x, a0[0]);
                        a0[1] = ffma2(wp0, sa.y, a0[1]);
                        a0[2] = ffma2(wp0, sb.x, a0[2]);
                        a0[3] = ffma2(wp0, sb.y, a0[3]);
                        a1[0] = ffma2(wp1, sa.x, a1[0]);
                        a1[1] = ffma2(wp1, sa.y, a1[1]);
                        a1[2] = ffma2(wp1, sb.x, a1[2]);
                        a1[3] = ffma2(wp1, sb.y, a1[3]);
                    }
                }
            }
            // gates layout: [gate 4][jp 4][mD 256] u64
            u64* guA = &un_s[((gpD * 2 + 0) * 4) * 256 + mD];
            u64* guB = &un_s[((gpD * 2 + 1) * 4) * 256 + mD];
            #pragma unroll
            for (int p = 0; p < 4; p++) { guA[p * 256] = a0[p]; guB[p * 256] = a1[p]; }
        }
        GBAR(gid);

        // ---------- Phase D epilogue: (mD, 4 j) ----------
        {
            float gv[4][4];    // [gate][jj]
            #pragma unroll
            for (int g = 0; g < 4; g++) {
                u64 v0 = un_s[(g * 4 + jq * 2 + 0) * 256 + mD];
                u64 v1 = un_s[(g * 4 + jq * 2 + 1) * 256 + mD];
                unpack2(v0, gv[g][0], gv[g][1]);
                unpack2(v1, gv[g][2], gv[g][3]);
            }
            float4 coldv = *(const float4*)&c_s[mD * GST + j0];
            float cnv[4], hnv[4];
            #pragma unroll
            for (int jj = 0; jj < 4; jj++) {
                float cold = (&coldv.x)[jj];
                float cn = sigmoid_fast(gv[1][jj]) * cold
                         + sigmoid_fast(gv[0][jj]) * tanh_fast(gv[2][jj]);
                float hn = sigmoid_fast(gv[3][jj]) * tanh_fast(cn);
                cnv[jj] = cn; hnv[jj] = hn;
                stcs(&out[(size_t)(b0g + j0 + jj) * (MM * TT) + (size_t)mD * TT + t], hn);
            }
            *(float4*)&c_s[mD * GST + j0] = make_float4(cnv[0], cnv[1], cnv[2], cnv[3]);
            *(float4*)&h_s[mD * GST + j0] = make_float4(hnv[0], hnv[1], hnv[2], hnv[3]);
        }
        GBAR(gid);   // state visible before next step's A1/D reads
    }
}

extern "C" void kernel_launch(void* const* d_in, const int* in_sizes, int n_in,
                              void* d_out, int out_size)
{
    const float* x    = (const float*)d_in[0];
    const float* W_e  = (const float*)d_in[1];
    const float* U_e  = (const float*)d_in[2];
    const float* V_e  = (const float*)d_in[3];
    const float* W_ih = (const float*)d_in[4];
    const float* W_hh = (const float*)d_in[5];
    const float* b_ih = (const float*)d_in[6];
    const float* b_hh = (const float*)d_in[7];
    float* out = (float*)d_out;

    const int smem1 = (TT * NN) * 4 + 64 * 128 * 8;                      // 196608
    // 3 state arrays [2][256][8] + e [2][8][256] + bias + V  -> floats
    const int smem2 = (6 * MM * GST + 2 * GB * NN + GG4 + TT) * 4
                    + 2 * TT * GB * 4        // whs2
                    + 2 * 4096 * 8;          // un_s
    // = (12288+4096+1024+128)*4 + 8192 + 65536 = 143,872 B

    cudaFuncSetAttribute(ux_kernel,  cudaFuncAttributeMaxDynamicSharedMemorySize, smem1);
    cudaFuncSetAttribute(rec_kernel, cudaFuncAttributeMaxDynamicSharedMemorySize, smem2);

    // trailing blocks: (64*1024 + 16*128) / 256 = 264
    ux_kernel<<<BSZ + 264, 256, smem1>>>(x, U_e, W_ih, W_hh, W_e);
    rec_kernel<<<NBLK, NTHR, smem2>>>(V_e, b_ih, b_hh, out);
}

// round 16
// speedup vs baseline: 1.7384x; 1.7384x over previous
#include <cuda_runtime.h>
#include <cuda_fp16.h>

#define BSZ    2048
#define TT     128
#define NN     256
#define MM     256
#define GG4    1024
#define B_TILE 16
#define NBLK   (BSZ / B_TILE)  /* 128 */
#define NTHR   1024

// ---------------- device scratch ----------------
__device__ __half g_Ux[(size_t)BSZ * TT * NN];   // [b][s][n] fp16, 134 MB
__device__ uint4  g_WfD[32 * 64 * 32];           // [kt][mt][lane] HMMA A-frags of [W_ih|W_hh] (1 MB)
__device__ uint4  g_WfA[32 * 8 * 32];            // [kt][mt][lane] HMMA A-frags of W_e (128 KB)

// ---------------- fast math ----------------
__device__ __forceinline__ float ex2f(float x) {
    float r; asm("ex2.approx.f32 %0, %1;" : "=f"(r) : "f"(x)); return r;
}
__device__ __forceinline__ float rcpf(float x) {
    float r; asm("rcp.approx.f32 %0, %1;" : "=f"(r) : "f"(x)); return r;
}
#define L2E 1.4426950408889634f
__device__ __forceinline__ float tanh_fast(float x) {
    float t = ex2f(2.0f * L2E * x);
    return 1.0f - 2.0f * rcpf(t + 1.0f);
}
__device__ __forceinline__ float sigmoid_fast(float x) {
    return rcpf(1.0f + ex2f(-L2E * x));
}
__device__ __forceinline__ unsigned tanh2_h(unsigned x) {
    unsigned r; asm("tanh.approx.f16x2 %0, %1;" : "=r"(r) : "r"(x)); return r;
}

// ---------------- packed f32x2 (ux_kernel only) ----------------
typedef unsigned long long u64;
__device__ __forceinline__ u64 pack2(float a, float b) {
    u64 r; asm("mov.b64 %0, {%1, %2};" : "=l"(r) : "f"(a), "f"(b)); return r;
}
__device__ __forceinline__ void unpack2(u64 v, float& a, float& b) {
    asm("mov.b64 {%0, %1}, %2;" : "=f"(a), "=f"(b) : "l"(v));
}
__device__ __forceinline__ u64 ffma2(u64 a, u64 b, u64 c) {
    u64 d; asm("fma.rn.f32x2 %0, %1, %2, %3;" : "=l"(d) : "l"(a), "l"(b), "l"(c)); return d;
}
__device__ __forceinline__ void stcs(float* p, float v) {
    asm volatile("st.global.cs.f32 [%0], %1;" :: "l"(p), "f"(v) : "memory");
}
__device__ __forceinline__ unsigned pack_h2f(float lo, float hi) {
    __half2 h = __floats2half2_rn(lo, hi);
    return *(unsigned*)&h;
}
__device__ __forceinline__ unsigned dup_h2(float v) {
    __half2 h = __half2half2(__float2half_rn(v));
    return *(unsigned*)&h;
}
__device__ __forceinline__ unsigned s2u(const void* p) {
    return (unsigned)__cvta_generic_to_shared(p);
}
// ---------------- tensor-core primitives ----------------
__device__ __forceinline__ void ldsm4t(unsigned a, unsigned& r0, unsigned& r1, unsigned& r2, unsigned& r3) {
    asm volatile("ldmatrix.sync.aligned.m8n8.x4.trans.shared.b16 {%0,%1,%2,%3}, [%4];"
                 : "=r"(r0), "=r"(r1), "=r"(r2), "=r"(r3) : "r"(a));
}
__device__ __forceinline__ void ldsm2t(unsigned a, unsigned& r0, unsigned& r1) {
    asm volatile("ldmatrix.sync.aligned.m8n8.x2.trans.shared.b16 {%0,%1}, [%2];"
                 : "=r"(r0), "=r"(r1) : "r"(a));
}
__device__ __forceinline__ void mma16816(float* d, const uint4& a, unsigned b0, unsigned b1) {
    asm volatile("mma.sync.aligned.m16n8k16.row.col.f32.f16.f16.f32 "
                 "{%0,%1,%2,%3}, {%4,%5,%6,%7}, {%8,%9}, {%0,%1,%2,%3};"
                 : "+f"(d[0]), "+f"(d[1]), "+f"(d[2]), "+f"(d[3])
                 : "r"(a.x), "r"(a.y), "r"(a.z), "r"(a.w), "r"(b0), "r"(b1));
}

// =====================================================================
// Kernel 1: Ux precompute + fragment-ordered fp16 weight pack (trailing).
// =====================================================================
__global__ void __launch_bounds__(256, 1) ux_kernel(
    const float* __restrict__ x,    const float* __restrict__ U_e,
    const float* __restrict__ W_ih, const float* __restrict__ W_hh,
    const float* __restrict__ W_e)
{
    if (blockIdx.x >= BSZ) {   // ---- pack weights into HMMA A-fragment order ----
        int idx = (blockIdx.x - BSZ) * 256 + threadIdx.x;
        int lane = idx & 31;
        int g = lane >> 2, tg = lane & 3;
        if (idx < 65536) {                      // gates W: [kt 32][mt 64][lane 32]
            int mtkt = idx >> 5;
            int mt = mtkt & 63, kt = mtkt >> 6;
            uint4 o;
            #pragma unroll
            for (int q = 0; q < 4; q++) {
                int r = mt * 16 + g + (q & 1) * 8;
                int k = kt * 16 + 2 * tg + (q >> 1) * 8;
                float lo, hi;
                if (k < 256) { lo = W_ih[r * 256 + k];       hi = W_ih[r * 256 + k + 1]; }
                else         { lo = W_hh[r * 256 + k - 256]; hi = W_hh[r * 256 + k - 255]; }
                ((unsigned*)&o)[q] = pack_h2f(lo, hi);
            }
            g_WfD[idx] = o;
        } else if (idx < 65536 + 8192) {        // W_e: [kt 32][mt 8][lane 32]
            int i2 = idx - 65536;
            int mtkt = i2 >> 5;
            int mt = mtkt & 7, kt = mtkt >> 3;
            uint4 o;
            #pragma unroll
            for (int q = 0; q < 4; q++) {
                int s = mt * 16 + g + (q & 1) * 8;
                int k = kt * 16 + 2 * tg + (q >> 1) * 8;
                ((unsigned*)&o)[q] = pack_h2f(W_e[s * 512 + k], W_e[s * 512 + k + 1]);
            }
            g_WfA[i2] = o;
        }
        return;
    }

    extern __shared__ float sm[];
    float* x_s  = sm;                    // [TT][NN]
    u64*   U2_s = (u64*)(sm + TT * NN);  // [64 s-pairs][128 t]
    float* U2f  = (float*)U2_s;

    const int b   = blockIdx.x;
    const int tid = threadIdx.x;

    const float4* xg = (const float4*)(x + (size_t)b * TT * NN);
    float4* xs4 = (float4*)x_s;
    for (int i = tid; i < TT * NN / 4; i += 256) xs4[i] = xg[i];

    for (int i = tid; i < TT * TT / 4; i += 256) {
        float4 v = ((const float4*)U_e)[i];
        int s  = i >> 5;
        int t0 = (i & 31) * 4;
        #pragma unroll
        for (int q = 0; q < 4; q++)
            U2f[(((s >> 1) * 128) + (t0 + q)) * 2 + (s & 1)] = (&v.x)[q];
    }
    __syncthreads();

    const int n = tid;
    for (int chunk = 0; chunk < 8; chunk++) {
        u64 acc[8];
        #pragma unroll
        for (int i = 0; i < 8; i++) acc[i] = 0ull;
        #pragma unroll 2
        for (int t = 0; t < TT; t++) {
            float xv = x_s[t * NN + n];
            u64 xp = pack2(xv, xv);
            #pragma unroll
            for (int i = 0; i < 8; i++)
                acc[i] = ffma2(U2_s[(chunk * 8 + i) * 128 + t], xp, acc[i]);
        }
        #pragma unroll
        for (int i = 0; i < 8; i++) {
            float a, bb; unpack2(acc[i], a, bb);
            #pragma unroll
            for (int h = 0; h < 2; h++) {
                float v = h ? bb : a;
                int s = chunk * 16 + 2 * i + h;
                float vn = __shfl_down_sync(0xffffffffu, v, 1);
                if ((n & 1) == 0) {
                    __half2 hv = __floats2half2_rn(v, vn);
                    *((__half2*)(g_Ux + ((size_t)b * TT + s) * NN + n)) = hv;
                }
            }
        }
    }
}

// =====================================================================
// Kernel 2: persistent recurrence, HMMA phases A and D.
// 128 CTAs x 1024 threads (32 warps), 16 batches = MMA N dimension.
// =====================================================================
__global__ void __launch_bounds__(NTHR, 1) rec_kernel(
    const float* __restrict__ V_e,
    const float* __restrict__ b_ih, const float* __restrict__ b_hh,
    float* __restrict__ out)
{
    extern __shared__ float sm[];
    float*    c32   = sm;                           // [256][20] fp32 cell master
    float*    gates = c32 + 256 * 20;               // [1024][20] fp32
    float*    e_s   = gates + 1024 * 20;            // [16][256]
    float*    bs_s  = e_s + 16 * 256;               // [1024]
    float*    V_s   = bs_s + GG4;                   // [128]
    unsigned* whs2  = (unsigned*)(V_s + TT);        // [128][20] half2(w,w)
    __half*   xtH   = (__half*)(whs2 + TT * 20);    // [256][24]
    __half*   hH    = xtH + 256 * 24;               // [256][24]
    __half*   hLo   = hH  + 256 * 24;               // [256][24] h residual
    __half*   cH    = hLo + 256 * 24;               // [256][24]

    const int tid = threadIdx.x;
    const int b0  = blockIdx.x * B_TILE;
    const int w   = tid >> 5, l = tid & 31;
    const int g   = l >> 2,  tg = l & 3;

    for (int i = tid; i < 256 * 20; i += NTHR) c32[i] = 0.0f;
    {   // zero xtH/hH/hLo/cH (4 * 256 * 24 halves = 6144 words)
        unsigned* hz = (unsigned*)xtH;
        for (int i = tid; i < 4 * 256 * 12; i += NTHR) hz[i] = 0u;
    }
    for (int i = tid; i < TT;  i += NTHR) V_s[i]  = V_e[i];
    for (int i = tid; i < GG4; i += NTHR) bs_s[i] = b_ih[i] + b_hh[i];
    __syncthreads();

    // phase B mapping
    const int np  = tid & 127;
    const int n0  = np * 2;
    const int jg  = tid >> 7;                   // 0..7, 2 batches each
    // epilogue mapping
    const int mD  = tid & 255;
    const int j0  = (tid >> 8) * 4;             // 0,4,8,12

    const __half2* ux2[2];
    #pragma unroll
    for (int jj = 0; jj < 2; jj++)
        ux2[jj] = (const __half2*)(g_Ux + ((size_t)(b0 + jg * 2 + jj) * TT) * NN + n0);

    const unsigned xtB = s2u(xtH), hHB = s2u(hH), hLoB = s2u(hLo), cHB = s2u(cH);
    const int krl = l & 15;
    const unsigned nco = (unsigned)((l >> 4) * 16);  // n-offset bytes for ldmatrix.x4

    // phase D bias (rows w*16+g(+8) and (w+32)*16+g(+8))
    const float bi00 = bs_s[w * 16 + g],          bi01 = bs_s[w * 16 + g + 8];
    const float bi10 = bs_s[(w + 32) * 16 + g],   bi11 = bs_s[(w + 32) * 16 + g + 8];

    for (int t = 0; t < TT; t++) {
        // ---------- Phase A: whs = W_e @ [h;c]  (HMMA, warps 0-15) ----------
        if (w < 16) {
            const int mt = w >> 1, nb = w & 1;
            float dA[4] = {0.0f, 0.0f, 0.0f, 0.0f};
            #pragma unroll 4
            for (int kt = 0; kt < 32; kt++) {
                uint4 av = g_WfA[(kt * 8 + mt) * 32 + l];
                unsigned base = (kt < 16) ? hHB : cHB;
                unsigned ba = base + (unsigned)(((kt & 15) * 16 + krl) * 48 + nb * 16);
                unsigned b0r, b1r;
                ldsm2t(ba, b0r, b1r);
                mma16816(dA, av, b0r, b1r);
            }
            const int s0 = mt * 16 + g;
            const int jj = nb * 8 + 2 * tg;
            whs2[s0 * 20 + jj]           = dup_h2(dA[0]);
            whs2[s0 * 20 + jj + 1]       = dup_h2(dA[1]);
            whs2[(s0 + 8) * 20 + jj]     = dup_h2(dA[2]);
            whs2[(s0 + 8) * 20 + jj + 1] = dup_h2(dA[3]);
        }
        __syncthreads();

        // ---------- Phase B: e[j][n] = sum_s V[s] * tanh(Ux + whs) ----------
        {
            float ex0[2] = {0, 0}, ex1[2] = {0, 0};
            #pragma unroll 4
            for (int s = 0; s < TT; s++) {
                uint2 wpk = *(const uint2*)&whs2[s * 20 + jg * 2];  // (j, j+1) half2-dups
                float vs = V_s[s];
                #pragma unroll
                for (int jj = 0; jj < 2; jj++) {
                    __half2 u   = ux2[jj][s * (NN / 2)];
                    __half2 wv  = *(__half2*)(((unsigned*)&wpk) + jj);
                    __half2 arg = __hadd2(u, wv);
                    unsigned th = tanh2_h(*(unsigned*)&arg);
                    float2 f = __half22float2(*(__half2*)&th);
                    ex0[jj] = fmaf(vs, f.x, ex0[jj]);
                    ex1[jj] = fmaf(vs, f.y, ex1[jj]);
                }
            }
            #pragma unroll
            for (int jj = 0; jj < 2; jj++)
                *(float2*)&e_s[(jg * 2 + jj) * NN + n0] = make_float2(ex0[jj], ex1[jj]);
        }
        __syncthreads();

        // ---------- Phase C: softmax over n, xt = alpha*e -> xtH fp16 ----------
        if (w < B_TILE) {
            const int j = w;
            float ev[8];
            float mx = -3.4e38f;
            #pragma unroll
            for (int i = 0; i < 8; i++) {
                ev[i] = e_s[j * NN + l + 32 * i];
                mx = fmaxf(mx, ev[i]);
            }
            #pragma unroll
            for (int o = 16; o > 0; o >>= 1) mx = fmaxf(mx, __shfl_xor_sync(0xffffffffu, mx, o));
            float ax[8], sum = 0.0f;
            #pragma unroll
            for (int i = 0; i < 8; i++) { ax[i] = ex2f((ev[i] - mx) * L2E); sum += ax[i]; }
            #pragma unroll
            for (int o = 16; o > 0; o >>= 1) sum += __shfl_xor_sync(0xffffffffu, sum, o);
            float inv = rcpf(sum);
            #pragma unroll
            for (int i = 0; i < 8; i++)
                xtH[(l + 32 * i) * 24 + j] = __float2half_rn((ax[i] * inv) * ev[i]);
        }
        __syncthreads();

        // ---------- Phase D: gates = [W_ih|W_hh] @ [xt; h_hi+h_lo]  (HMMA, all warps) ----------
        {
            float d00[4] = {bi00, bi00, bi01, bi01};   // mt0, nb0
            float d01[4] = {bi00, bi00, bi01, bi01};   // mt0, nb1
            float d10[4] = {bi10, bi10, bi11, bi11};   // mt1, nb0
            float d11[4] = {bi10, bi10, bi11, bi11};   // mt1, nb1

            #pragma unroll 2
            for (int kt = 0; kt < 16; kt++) {          // xt ktiles
                uint4 a0 = g_WfD[(kt * 64 + w) * 32 + l];
                uint4 a1 = g_WfD[(kt * 64 + w + 32) * 32 + l];
                unsigned ba = xtB + (unsigned)((kt * 16 + krl) * 48) + nco;
                unsigned b0r, b1r, b2r, b3r;
                ldsm4t(ba, b0r, b1r, b2r, b3r);
                mma16816(d00, a0, b0r, b1r);
                mma16816(d01, a0, b2r, b3r);
                mma16816(d10, a1, b0r, b1r);
                mma16816(d11, a1, b2r, b3r);
            }
            #pragma unroll 2
            for (int kt = 16; kt < 32; kt++) {         // h ktiles (hi + lo split)
                uint4 a0 = g_WfD[(kt * 64 + w) * 32 + l];
                uint4 a1 = g_WfD[(kt * 64 + w + 32) * 32 + l];
                unsigned off = (unsigned)(((kt - 16) * 16 + krl) * 48) + nco;
                unsigned h0, h1, h2, h3, q0, q1, q2, q3;
                ldsm4t(hHB + off, h0, h1, h2, h3);
                ldsm4t(hLoB + off, q0, q1, q2, q3);
                mma16816(d00, a0, h0, h1);
                mma16816(d01, a0, h2, h3);
                mma16816(d10, a1, h0, h1);
                mma16816(d11, a1, h2, h3);
                mma16816(d00, a0, q0, q1);
                mma16816(d01, a0, q2, q3);
                mma16816(d10, a1, q0, q1);
                mma16816(d11, a1, q2, q3);
            }
            // store gate fragments: rows mt0 = w*16.., mt1 = (w+32)*16..
            const int rb0 = w * 16, rb1 = (w + 32) * 16;
            const int jjn0 = 2 * tg, jjn1 = 8 + 2 * tg;
            *(float2*)&gates[(rb0 + g) * 20 + jjn0]     = make_float2(d00[0], d00[1]);
            *(float2*)&gates[(rb0 + g + 8) * 20 + jjn0] = make_float2(d00[2], d00[3]);
            *(float2*)&gates[(rb0 + g) * 20 + jjn1]     = make_float2(d01[0], d01[1]);
            *(float2*)&gates[(rb0 + g + 8) * 20 + jjn1] = make_float2(d01[2], d01[3]);
            *(float2*)&gates[(rb1 + g) * 20 + jjn0]     = make_float2(d10[0], d10[1]);
            *(float2*)&gates[(rb1 + g + 8) * 20 + jjn0] = make_float2(d10[2], d10[3]);
            *(float2*)&gates[(rb1 + g) * 20 + jjn1]     = make_float2(d11[0], d11[1]);
            *(float2*)&gates[(rb1 + g + 8) * 20 + jjn1] = make_float2(d11[2], d11[3]);
        }
        __syncthreads();

        // ---------- Epilogue: LSTM update, (mD, 4 j) per thread ----------
        {
            float4 gi = *(float4*)&gates[(0   + mD) * 20 + j0];
            float4 gf = *(float4*)&gates[(256 + mD) * 20 + j0];
            float4 gg = *(float4*)&gates[(512 + mD) * 20 + j0];
            float4 go = *(float4*)&gates[(768 + mD) * 20 + j0];
            float4 cold = *(float4*)&c32[mD * 20 + j0];
            float cn[4], hn[4], lo[4];
            __half hh[4];
            #pragma unroll
            for (int jj = 0; jj < 4; jj++) {
                float cv = sigmoid_fast((&gf.x)[jj]) * (&cold.x)[jj]
                         + sigmoid_fast((&gi.x)[jj]) * tanh_fast((&gg.x)[jj]);
                float hv = sigmoid_fast((&go.x)[jj]) * tanh_fast(cv);
                cn[jj] = cv; hn[jj] = hv;
                hh[jj] = __float2half_rn(hv);
                lo[jj] = hv - __half2float(hh[jj]);
                stcs(&out[(size_t)(b0 + j0 + jj) * (MM * TT) + (size_t)mD * TT + t], hv);
            }
            *(float4*)&c32[mD * 20 + j0] = make_float4(cn[0], cn[1], cn[2], cn[3]);
            __half2 c01 = __floats2half2_rn(cn[0], cn[1]), c23 = __floats2half2_rn(cn[2], cn[3]);
            __half2 h01 = __halves2half2(hh[0], hh[1]),    h23 = __halves2half2(hh[2], hh[3]);
            __half2 l01 = __floats2half2_rn(lo[0], lo[1]), l23 = __floats2half2_rn(lo[2], lo[3]);
            *(uint2*)&cH [mD * 24 + j0] = make_uint2(*(unsigned*)&c01, *(unsigned*)&c23);
            *(uint2*)&hH [mD * 24 + j0] = make_uint2(*(unsigned*)&h01, *(unsigned*)&h23);
            *(uint2*)&hLo[mD * 24 + j0] = make_uint2(*(unsigned*)&l01, *(unsigned*)&l23);
        }
        __syncthreads();   // state visible before next step's A/D reads
    }
}

extern "C" void kernel_launch(void* const* d_in, const int* in_sizes, int n_in,
                              void* d_out, int out_size)
{
    const float* x    = (const float*)d_in[0];
    const float* W_e  = (const float*)d_in[1];
    const float* U_e  = (const float*)d_in[2];
    const float* V_e  = (const float*)d_in[3];
    const float* W_ih = (const float*)d_in[4];
    const float* W_hh = (const float*)d_in[5];
    const float* b_ih = (const float*)d_in[6];
    const float* b_hh = (const float*)d_in[7];
    float* out = (float*)d_out;

    const int smem1 = (TT * NN) * 4 + 64 * 128 * 8;   // 196608
    // c32 + gates + e + bias + V  (floats) + whs2 (u32) + 4 half arrays
    const int smem2 = (256 * 20 + 1024 * 20 + 16 * 256 + GG4 + TT) * 4
                    + TT * 20 * 4
                    + 4 * 256 * 24 * 2;               // 182784 B

    cudaFuncSetAttribute(ux_kernel,  cudaFuncAttributeMaxDynamicSharedMemorySize, smem1);
    cudaFuncSetAttribute(rec_kernel, cudaFuncAttributeMaxDynamicSharedMemorySize, smem2);

    // trailing blocks: (65536 + 8192) / 256 = 288
    ux_kernel<<<BSZ + 288, 256, smem1>>>(x, U_e, W_ih, W_hh, W_e);
    rec_kernel<<<NBLK, NTHR, smem2>>>(V_e, b_ih, b_hh, out);
}